// round 15
// baseline (speedup 1.0000x reference)
#include <cuda_runtime.h>
#include <math.h>
#include <stdint.h>

#define B_   2
#define S_   2048
#define D_   1024
#define H_   16
#define MS_  (B_*S_)        // 4096 rows
#define NQ_  (2*D_)         // 2048
#define QST  68             // attn Q/K/P row stride (floats)
#define VST  72             // attn V row stride (floats)
#define GST  36             // gemm smem row stride (floats)
#define LAMBDA_INIT 0.2f
#define SCALE_QK 0.125f

// ---------------- scratch ----------------
__device__ float g_q[MS_ * NQ_];
__device__ float g_k[MS_ * NQ_];
__device__ float g_v[MS_ * D_];
__device__ float g_y[MS_ * D_];
__device__ float g_lam[H_];
__device__ float g_cos[S_ * 32];
__device__ float g_sin[S_ * 32];

// ---------------- helpers ----------------
__device__ __forceinline__ float to_tf32(float x) {
    uint32_t u;
    asm("cvt.rna.tf32.f32 %0, %1;\n" : "=r"(u) : "f"(x));
    return __uint_as_float(u);
}
__device__ __forceinline__ void mma_tf32(float* d, float a0, float a1, float a2, float a3,
                                         float b0, float b1) {
    asm volatile("mma.sync.aligned.m16n8k8.row.col.f32.tf32.tf32.f32 "
                 "{%0,%1,%2,%3},{%4,%5,%6,%7},{%8,%9},{%0,%1,%2,%3};\n"
                 : "+f"(d[0]), "+f"(d[1]), "+f"(d[2]), "+f"(d[3])
                 : "r"(__float_as_uint(a0)), "r"(__float_as_uint(a1)),
                   "r"(__float_as_uint(a2)), "r"(__float_as_uint(a3)),
                   "r"(__float_as_uint(b0)), "r"(__float_as_uint(b1)));
}

// ---------------- RoPE table ----------------
__global__ void rope_table_kernel() {
    const int s = blockIdx.x;
    const int d = threadIdx.x;
    float invf = (float)pow(10000.0, -(double)d / 32.0);
    float angf = (float)s * invf;
    double cd, sd;
    sincos((double)angf, &cd, &sd);
    g_cos[s * 32 + d] = (float)cd;
    g_sin[s * 32 + d] = -(float)sd;   // flipped rotation (verified)
}

// ---------------- RoPE apply, fp32 in place ----------------
__global__ void rope_kernel() {
    const int r = blockIdx.x;
    const int h = threadIdx.x >> 5;
    const int d = threadIdx.x & 31;
    const int s = r & (S_ - 1);
    const float c  = g_cos[s * 32 + d];
    const float sn = g_sin[s * 32 + d];
    const size_t base = (size_t)r * NQ_ + h * 128;
    {
        float x1 = g_q[base + d], x2 = g_q[base + d + 32];
        g_q[base + d]      = x1 * c - x2 * sn;
        g_q[base + d + 32] = x1 * sn + x2 * c;
    }
    {
        float x1 = g_q[base + 64 + d], x2 = g_q[base + 96 + d];
        g_q[base + 64 + d] = x1 * c - x2 * sn;
        g_q[base + 96 + d] = x1 * sn + x2 * c;
    }
    {
        float x1 = g_k[base + d], x2 = g_k[base + d + 32];
        g_k[base + d]      = x1 * c - x2 * sn;
        g_k[base + d + 32] = x1 * sn + x2 * c;
    }
    {
        float x1 = g_k[base + 64 + d], x2 = g_k[base + 96 + d];
        g_k[base + 64 + d] = x1 * c - x2 * sn;
        g_k[base + 96 + d] = x1 * sn + x2 * c;
    }
}

// ---------------- TF32 GEMM, 512 threads: C = A @ W^T + bias ----------------
// 128x128 block tile, K-tile 32; 16 warps (4m x 4n), warp tile 32x32.
__global__ __launch_bounds__(512, 1) void gemm_tf32(const float* __restrict__ A,
                                                    const float* __restrict__ W,
                                                    const float* __restrict__ bias,
                                                    float* __restrict__ C,
                                                    int M, int N, int K) {
    extern __shared__ __align__(16) float gsm[];
    float* sA = gsm;                        // 2 x 128*GST
    float* sW = gsm + 2 * 128 * GST;        // 2 x 128*GST

    const int tid = threadIdx.x;
    const int w = tid >> 5, lane = tid & 31;
    const int wm = w >> 2, wn = w & 3;
    const int g = lane >> 2, tig = lane & 3;
    const int row0 = blockIdx.y * 128;
    const int col0 = blockIdx.x * 128;

    const int lr = tid >> 3;            // 0..63
    const int lc = (tid & 7) << 2;      // 0,4,..28

    float acc[2][4][4];
#pragma unroll
    for (int mt = 0; mt < 2; mt++)
#pragma unroll
        for (int nt = 0; nt < 4; nt++)
#pragma unroll
            for (int i = 0; i < 4; i++) acc[mt][nt][i] = 0.f;

    const int T = K / 32;

    // preload tile 0
#pragma unroll
    for (int i = 0; i < 2; i++) {
        int r = lr + i * 64;
        float4 av = *(const float4*)&A[(size_t)(row0 + r) * K + lc];
        float4 wv = *(const float4*)&W[(size_t)(col0 + r) * K + lc];
        float* da = sA + r * GST + lc;
        float* dw = sW + r * GST + lc;
        da[0] = to_tf32(av.x); da[1] = to_tf32(av.y); da[2] = to_tf32(av.z); da[3] = to_tf32(av.w);
        dw[0] = to_tf32(wv.x); dw[1] = to_tf32(wv.y); dw[2] = to_tf32(wv.z); dw[3] = to_tf32(wv.w);
    }
    __syncthreads();

    for (int t = 0; t < T; t++) {
        const int cur = t & 1;
        float4 av[2], wv[2];
        if (t + 1 < T) {
            const int k0 = (t + 1) * 32;
#pragma unroll
            for (int i = 0; i < 2; i++) {
                int r = lr + i * 64;
                av[i] = *(const float4*)&A[(size_t)(row0 + r) * K + k0 + lc];
                wv[i] = *(const float4*)&W[(size_t)(col0 + r) * K + k0 + lc];
            }
        }

        const float* Ab = sA + cur * 128 * GST + (wm * 32 + g) * GST + tig;
        const float* Wb = sW + cur * 128 * GST + (wn * 32 + g) * GST + tig;
#pragma unroll
        for (int k8 = 0; k8 < 4; k8++) {
            const int ko = k8 * 8;
            float a[2][4];
#pragma unroll
            for (int mt = 0; mt < 2; mt++) {
                a[mt][0] = Ab[(mt * 16) * GST + ko];
                a[mt][1] = Ab[(mt * 16 + 8) * GST + ko];
                a[mt][2] = Ab[(mt * 16) * GST + ko + 4];
                a[mt][3] = Ab[(mt * 16 + 8) * GST + ko + 4];
            }
#pragma unroll
            for (int nt = 0; nt < 4; nt++) {
                float b0 = Wb[(nt * 8) * GST + ko];
                float b1 = Wb[(nt * 8) * GST + ko + 4];
#pragma unroll
                for (int mt = 0; mt < 2; mt++)
                    mma_tf32(acc[mt][nt], a[mt][0], a[mt][1], a[mt][2], a[mt][3], b0, b1);
            }
        }

        if (t + 1 < T) {
            const int nxt = 1 - cur;
            float* baseA = sA + nxt * 128 * GST;
            float* baseW = sW + nxt * 128 * GST;
            __syncthreads();
#pragma unroll
            for (int i = 0; i < 2; i++) {
                int r = lr + i * 64;
                float* da = baseA + r * GST + lc;
                float* dw = baseW + r * GST + lc;
                da[0] = to_tf32(av[i].x); da[1] = to_tf32(av[i].y);
                da[2] = to_tf32(av[i].z); da[3] = to_tf32(av[i].w);
                dw[0] = to_tf32(wv[i].x); dw[1] = to_tf32(wv[i].y);
                dw[2] = to_tf32(wv[i].z); dw[3] = to_tf32(wv[i].w);
            }
            __syncthreads();
        }
    }

    // epilogue: bias + store
#pragma unroll
    for (int nt = 0; nt < 4; nt++) {
        const int col = col0 + wn * 32 + nt * 8 + 2 * tig;
        float2 bb = *(const float2*)&bias[col];
#pragma unroll
        for (int mt = 0; mt < 2; mt++) {
            const int rowA = row0 + wm * 32 + mt * 16 + g;
            *(float2*)&C[(size_t)rowA * N + col] =
                make_float2(acc[mt][nt][0] + bb.x, acc[mt][nt][1] + bb.y);
            *(float2*)&C[(size_t)(rowA + 8) * N + col] =
                make_float2(acc[mt][nt][2] + bb.x, acc[mt][nt][3] + bb.y);
        }
    }
}

// ---------------- lambda ----------------
__global__ void lam_kernel(const float* __restrict__ lq1, const float* __restrict__ lk1,
                           const float* __restrict__ lq2, const float* __restrict__ lk2) {
    int h = threadIdx.x;
    if (h < H_) {
        float d1 = 0.f, d2 = 0.f;
        for (int i = 0; i < 64; i++) {
            d1 += lq1[h * 64 + i] * lk1[h * 64 + i];
            d2 += lq2[h * 64 + i] * lk2[h * 64 + i];
        }
        g_lam[h] = LAMBDA_INIT + expf(d1) - expf(d2);
    }
}

// ---------------- TF32 dual-stream causal attention, 512 threads ----------------
// 16 warps: st = w>>3 (stream), half = (w>>2)&1 (k-col half), wr = w&3 (16 q-rows).
// Each warp: S/exp/P for its 32 k-cols; partial O over its half; combine in epilogue.
__global__ __launch_bounds__(512, 1) void attn_kernel(const float* __restrict__ head_w) {
    extern __shared__ __align__(16) float smem[];
    float* sQ1 = smem;
    float* sQ2 = sQ1 + 64 * QST;
    float* sK1 = sQ2 + 64 * QST;
    float* sK2 = sK1 + 64 * QST;
    float* sP1 = sK2 + 64 * QST;
    float* sP2 = sP1 + 64 * QST;
    float* sV  = sP2 + 64 * QST;
    // epilogue aliases (dead storage at that point):
    float* scrH1 = sK1;     // stream1 half-combine, 64 x 66
    float* scrH2 = sK2;     // stream2 half-combine, 64 x 66
    float* sL    = sP1;     // 256 floats of partial row sums
    float* scrX  = sP2;     // stream exchange, 64 x 66

    const int p = blockIdx.x, h = blockIdx.y, b = blockIdx.z;
    const int tid = threadIdx.x;
    const int w = tid >> 5, lane = tid & 31;
    const int st = w >> 3, half = (w >> 2) & 1, wr = w & 3;
    const int g = lane >> 2, tig = lane & 3;
    const float lam = g_lam[h];

    float* sQ  = st ? sQ2 : sQ1;
    float* sKs = st ? sK2 : sK1;
    float* sP  = st ? sP2 : sP1;
    float* scrH = st ? scrH2 : scrH1;
    const int rAl = 16 * wr + g;

    for (int rep = 0; rep < 2; rep++) {
        const int qt = (rep == 0) ? p : (31 - p);

        // load Q tile (both streams), tf32-rounded, pre-scaled
#pragma unroll
        for (int i = 0; i < 4; i++) {
            int idx = tid + i * 512;
            int strm = idx >> 10;
            int r = (idx >> 4) & 63;
            int c4 = idx & 15;
            float4 v = *(const float4*)&g_q[(size_t)(b * S_ + qt * 64 + r) * NQ_ + h * 128 + strm * 64 + c4 * 4];
            float* dst = (strm ? sQ2 : sQ1) + r * QST + c4 * 4;
            dst[0] = to_tf32(v.x * SCALE_QK);
            dst[1] = to_tf32(v.y * SCALE_QK);
            dst[2] = to_tf32(v.z * SCALE_QK);
            dst[3] = to_tf32(v.w * SCALE_QK);
        }

        float o[8][4];
#pragma unroll
        for (int n = 0; n < 8; n++) { o[n][0] = o[n][1] = o[n][2] = o[n][3] = 0.f; }
        float lA = 0.f, lB = 0.f;

        for (int kt = 0; kt <= qt; kt++) {
            __syncthreads();
#pragma unroll
            for (int i = 0; i < 6; i++) {
                int idx = tid + i * 512;
                if (idx < 2048) {
                    int strm = idx >> 10;
                    int r = (idx >> 4) & 63;
                    int c4 = idx & 15;
                    float4 v = *(const float4*)&g_k[(size_t)(b * S_ + kt * 64 + r) * NQ_ + h * 128 + strm * 64 + c4 * 4];
                    float* dst = (strm ? sK2 : sK1) + r * QST + c4 * 4;
                    dst[0] = to_tf32(v.x); dst[1] = to_tf32(v.y);
                    dst[2] = to_tf32(v.z); dst[3] = to_tf32(v.w);
                } else {
                    int j = idx - 2048;
                    int r = j >> 4;
                    int c4 = j & 15;
                    float4 v = *(const float4*)&g_v[(size_t)(b * S_ + kt * 64 + r) * D_ + h * 64 + c4 * 4];
                    float* dst = sV + r * VST + c4 * 4;
                    dst[0] = to_tf32(v.x); dst[1] = to_tf32(v.y);
                    dst[2] = to_tf32(v.z); dst[3] = to_tf32(v.w);
                }
            }
            __syncthreads();

            // ---- S = Q·K^T for this warp's 32 k-cols ----
            float s[4][4];
#pragma unroll
            for (int n = 0; n < 4; n++) { s[n][0] = s[n][1] = s[n][2] = s[n][3] = 0.f; }
            const float* Qb = sQ + rAl * QST + tig;
            const float* Kb = sKs + (half * 32 + g) * QST + tig;
#pragma unroll
            for (int k8 = 0; k8 < 8; k8++) {
                const int ko = 8 * k8;
                float a0 = Qb[ko];
                float a1 = Qb[8 * QST + ko];
                float a2 = Qb[ko + 4];
                float a3 = Qb[8 * QST + ko + 4];
#pragma unroll
                for (int np = 0; np < 4; np++) {
                    float b0 = Kb[np * 8 * QST + ko];
                    float b1 = Kb[np * 8 * QST + ko + 4];
                    mma_tf32(s[np], a0, a1, a2, a3, b0, b1);
                }
            }

            // ---- mask + exp + partial row sums + store P ----
            const bool diag = (kt == qt);
            float sumA = 0.f, sumB = 0.f;
#pragma unroll
            for (int n = 0; n < 4; n++) {
                int c0 = half * 32 + 8 * n + 2 * tig;   // col within tile
                float p00, p01, p10, p11;
                if (diag) {
                    p00 = (c0     > rAl)     ? 0.f : __expf(s[n][0]);
                    p01 = (c0 + 1 > rAl)     ? 0.f : __expf(s[n][1]);
                    p10 = (c0     > rAl + 8) ? 0.f : __expf(s[n][2]);
                    p11 = (c0 + 1 > rAl + 8) ? 0.f : __expf(s[n][3]);
                } else {
                    p00 = __expf(s[n][0]); p01 = __expf(s[n][1]);
                    p10 = __expf(s[n][2]); p11 = __expf(s[n][3]);
                }
                sumA += p00 + p01;
                sumB += p10 + p11;
                *(float2*)&sP[rAl * QST + c0]       = make_float2(to_tf32(p00), to_tf32(p01));
                *(float2*)&sP[(rAl + 8) * QST + c0] = make_float2(to_tf32(p10), to_tf32(p11));
            }
            sumA += __shfl_xor_sync(0xffffffffu, sumA, 1);
            sumA += __shfl_xor_sync(0xffffffffu, sumA, 2);
            sumB += __shfl_xor_sync(0xffffffffu, sumB, 1);
            sumB += __shfl_xor_sync(0xffffffffu, sumB, 2);
            lA += sumA;   // own half only; combined in epilogue
            lB += sumB;
            __syncwarp();

            // ---- O += P·V over this warp's 32 k-rows ----
            const float* Pb = sP + rAl * QST + tig;
#pragma unroll
            for (int k8 = 0; k8 < 4; k8++) {
                const int ko = half * 32 + 8 * k8;
                float a0 = Pb[ko];
                float a1 = Pb[8 * QST + ko];
                float a2 = Pb[ko + 4];
                float a3 = Pb[8 * QST + ko + 4];
#pragma unroll
                for (int np = 0; np < 8; np++) {
                    float b0 = sV[(ko + tig) * VST + 8 * np + g];
                    float b1 = sV[(ko + tig + 4) * VST + 8 * np + g];
                    mma_tf32(o[np], a0, a1, a2, a3, b0, b1);
                }
            }
            __syncwarp();
        }

        // ---- epilogue ----
        __syncthreads();   // all mma done; sK/sP become scratch
        if (half == 1) {
            // publish raw partial O + partial sums
#pragma unroll
            for (int n = 0; n < 8; n++) {
                int c0 = 8 * n + 2 * tig;
                *(float2*)&scrH[rAl * 66 + c0]       = make_float2(o[n][0], o[n][1]);
                *(float2*)&scrH[(rAl + 8) * 66 + c0] = make_float2(o[n][2], o[n][3]);
            }
            if (tig == 0) {
                sL[st * 64 + rAl]     = lA;
                sL[st * 64 + rAl + 8] = lB;
            }
        }
        __syncthreads();
        if (half == 0) {
            // combine halves
            float lAt = lA + sL[st * 64 + rAl];
            float lBt = lB + sL[st * 64 + rAl + 8];
            float ot[8][4];
#pragma unroll
            for (int n = 0; n < 8; n++) {
                int c0 = 8 * n + 2 * tig;
                float2 hA = *(float2*)&scrH[rAl * 66 + c0];
                float2 hB = *(float2*)&scrH[(rAl + 8) * 66 + c0];
                ot[n][0] = o[n][0] + hA.x;
                ot[n][1] = o[n][1] + hA.y;
                ot[n][2] = o[n][2] + hB.x;
                ot[n][3] = o[n][3] + hB.y;
            }
            if (st == 1) {
                float fA = lam / lAt, fB = lam / lBt;
#pragma unroll
                for (int n = 0; n < 8; n++) {
                    int c0 = 8 * n + 2 * tig;
                    *(float2*)&scrX[rAl * 66 + c0]       = make_float2(ot[n][0] * fA, ot[n][1] * fA);
                    *(float2*)&scrX[(rAl + 8) * 66 + c0] = make_float2(ot[n][2] * fB, ot[n][3] * fB);
                }
            } else {
                // stash for phase 3 in registers; reuse o[]
#pragma unroll
                for (int n = 0; n < 8; n++) {
                    o[n][0] = ot[n][0]; o[n][1] = ot[n][1];
                    o[n][2] = ot[n][2]; o[n][3] = ot[n][3];
                }
                lA = lAt; lB = lBt;
            }
        }
        __syncthreads();
        if (half == 0 && st == 0) {
            float fA = 1.f / lA, fB = 1.f / lB;
            float oA[16], oB[16];
            float ssA = 0.f, ssB = 0.f;
#pragma unroll
            for (int n = 0; n < 8; n++) {
                int c0 = 8 * n + 2 * tig;
                float2 sA2 = *(float2*)&scrX[rAl * 66 + c0];
                float2 sB2 = *(float2*)&scrX[(rAl + 8) * 66 + c0];
                oA[2 * n]     = o[n][0] * fA - sA2.x;
                oA[2 * n + 1] = o[n][1] * fA - sA2.y;
                oB[2 * n]     = o[n][2] * fB - sB2.x;
                oB[2 * n + 1] = o[n][3] * fB - sB2.y;
                ssA += oA[2 * n] * oA[2 * n] + oA[2 * n + 1] * oA[2 * n + 1];
                ssB += oB[2 * n] * oB[2 * n] + oB[2 * n + 1] * oB[2 * n + 1];
            }
            ssA += __shfl_xor_sync(0xffffffffu, ssA, 1);
            ssA += __shfl_xor_sync(0xffffffffu, ssA, 2);
            ssB += __shfl_xor_sync(0xffffffffu, ssB, 1);
            ssB += __shfl_xor_sync(0xffffffffu, ssB, 2);
            float rnA = rsqrtf(ssA * (1.f / 64.f) + 1e-6f);
            float rnB = rsqrtf(ssB * (1.f / 64.f) + 1e-6f);

            size_t rowA = (size_t)(b * S_ + qt * 64 + rAl) * D_ + h * 64;
            size_t rowB = rowA + (size_t)8 * D_;
#pragma unroll
            for (int n = 0; n < 8; n++) {
                int c0 = 8 * n + 2 * tig;
                float2 hw2 = *(const float2*)&head_w[h * 64 + c0];
                *(float2*)&g_y[rowA + c0] =
                    make_float2(oA[2 * n] * rnA * hw2.x * 0.8f, oA[2 * n + 1] * rnA * hw2.y * 0.8f);
                *(float2*)&g_y[rowB + c0] =
                    make_float2(oB[2 * n] * rnB * hw2.x * 0.8f, oB[2 * n + 1] * rnB * hw2.y * 0.8f);
            }
        }
        __syncthreads();   // scratch reuse next rep / Q reload
    }
}

// ---------------- launch ----------------
extern "C" void kernel_launch(void* const* d_in, const int* in_sizes, int n_in,
                              void* d_out, int out_size) {
    const float* x   = (const float*)d_in[0];
    const float* Wq  = (const float*)d_in[1];
    const float* bq  = (const float*)d_in[2];
    const float* Wk  = (const float*)d_in[3];
    const float* bk  = (const float*)d_in[4];
    const float* Wv  = (const float*)d_in[5];
    const float* bv  = (const float*)d_in[6];
    const float* Wo  = (const float*)d_in[7];
    const float* bo  = (const float*)d_in[8];
    const float* hw  = (const float*)d_in[9];
    const float* lq1 = (const float*)d_in[10];
    const float* lk1 = (const float*)d_in[11];
    const float* lq2 = (const float*)d_in[12];
    const float* lk2 = (const float*)d_in[13];
    float* out = (float*)d_out;

    float *pq, *pk, *pv, *py;
    cudaGetSymbolAddress((void**)&pq, g_q);
    cudaGetSymbolAddress((void**)&pk, g_k);
    cudaGetSymbolAddress((void**)&pv, g_v);
    cudaGetSymbolAddress((void**)&py, g_y);

    const int smem_attn = (6 * 64 * QST + 64 * VST) * (int)sizeof(float);   // 122880 B
    cudaFuncSetAttribute(attn_kernel, cudaFuncAttributeMaxDynamicSharedMemorySize, smem_attn);
    const int smem_gemm = 4 * 128 * GST * (int)sizeof(float);               // 73728 B
    cudaFuncSetAttribute(gemm_tf32, cudaFuncAttributeMaxDynamicSharedMemorySize, smem_gemm);

    dim3 blk(512);
    rope_table_kernel<<<S_, 32>>>();
    gemm_tf32<<<dim3(NQ_ / 128, MS_ / 128), blk, smem_gemm>>>(x, Wq, bq, pq, MS_, NQ_, D_);
    gemm_tf32<<<dim3(NQ_ / 128, MS_ / 128), blk, smem_gemm>>>(x, Wk, bk, pk, MS_, NQ_, D_);
    gemm_tf32<<<dim3(D_ / 128, MS_ / 128), blk, smem_gemm>>>(x, Wv, bv, pv, MS_, D_, D_);
    rope_kernel<<<MS_, 512>>>();
    lam_kernel<<<1, 32>>>(lq1, lk1, lq2, lk2);
    attn_kernel<<<dim3(16, H_, B_), blk, smem_attn>>>(hw);
    gemm_tf32<<<dim3(D_ / 128, MS_ / 128), blk, smem_gemm>>>(py, Wo, bo, out, MS_, D_, D_);
}

// round 16
// speedup vs baseline: 1.0844x; 1.0844x over previous
#include <cuda_runtime.h>
#include <math.h>
#include <stdint.h>

#define B_   2
#define S_   2048
#define D_   1024
#define H_   16
#define MS_  (B_*S_)        // 4096 rows
#define NQ_  (2*D_)         // 2048
#define QST  68             // attn Q/K/P row stride (floats)
#define VST  72             // attn V row stride (floats)
#define GST  36             // gemm smem row stride (floats)
#define LAMBDA_INIT 0.2f
#define SCALE_QK 0.125f

// ---------------- scratch ----------------
__device__ float g_q[MS_ * NQ_];
__device__ float g_k[MS_ * NQ_];
__device__ float g_v[MS_ * D_];
__device__ float g_y[MS_ * D_];
__device__ float g_lam[H_];
__device__ float g_cos[S_ * 32];
__device__ float g_sin[S_ * 32];

// ---------------- helpers ----------------
__device__ __forceinline__ float to_tf32(float x) {
    uint32_t u;
    asm("cvt.rna.tf32.f32 %0, %1;\n" : "=r"(u) : "f"(x));
    return __uint_as_float(u);
}
__device__ __forceinline__ void mma_tf32(float* d, float a0, float a1, float a2, float a3,
                                         float b0, float b1) {
    asm volatile("mma.sync.aligned.m16n8k8.row.col.f32.tf32.tf32.f32 "
                 "{%0,%1,%2,%3},{%4,%5,%6,%7},{%8,%9},{%0,%1,%2,%3};\n"
                 : "+f"(d[0]), "+f"(d[1]), "+f"(d[2]), "+f"(d[3])
                 : "r"(__float_as_uint(a0)), "r"(__float_as_uint(a1)),
                   "r"(__float_as_uint(a2)), "r"(__float_as_uint(a3)),
                   "r"(__float_as_uint(b0)), "r"(__float_as_uint(b1)));
}

// ---------------- RoPE table ----------------
__global__ void rope_table_kernel() {
    const int s = blockIdx.x;
    const int d = threadIdx.x;
    float invf = (float)pow(10000.0, -(double)d / 32.0);
    float angf = (float)s * invf;
    double cd, sd;
    sincos((double)angf, &cd, &sd);
    g_cos[s * 32 + d] = (float)cd;
    g_sin[s * 32 + d] = -(float)sd;   // flipped rotation (verified)
}

// ---------------- RoPE apply, fp32 in place ----------------
__global__ void rope_kernel() {
    const int r = blockIdx.x;
    const int h = threadIdx.x >> 5;
    const int d = threadIdx.x & 31;
    const int s = r & (S_ - 1);
    const float c  = g_cos[s * 32 + d];
    const float sn = g_sin[s * 32 + d];
    const size_t base = (size_t)r * NQ_ + h * 128;
    {
        float x1 = g_q[base + d], x2 = g_q[base + d + 32];
        g_q[base + d]      = x1 * c - x2 * sn;
        g_q[base + d + 32] = x1 * sn + x2 * c;
    }
    {
        float x1 = g_q[base + 64 + d], x2 = g_q[base + 96 + d];
        g_q[base + 64 + d] = x1 * c - x2 * sn;
        g_q[base + 96 + d] = x1 * sn + x2 * c;
    }
    {
        float x1 = g_k[base + d], x2 = g_k[base + d + 32];
        g_k[base + d]      = x1 * c - x2 * sn;
        g_k[base + d + 32] = x1 * sn + x2 * c;
    }
    {
        float x1 = g_k[base + 64 + d], x2 = g_k[base + 96 + d];
        g_k[base + 64 + d] = x1 * c - x2 * sn;
        g_k[base + 96 + d] = x1 * sn + x2 * c;
    }
}

// ---------------- TF32 GEMM: C = A @ W^T + bias ----------------
// CTA tile 256x128, K-tile 32; 8 warps (4m x 2n), warp tile 64x64.
__global__ __launch_bounds__(256, 1) void gemm_tf32(const float* __restrict__ A,
                                                    const float* __restrict__ W,
                                                    const float* __restrict__ bias,
                                                    float* __restrict__ C,
                                                    int M, int N, int K) {
    extern __shared__ __align__(16) float gsm[];
    float* sA = gsm;                        // 2 x 256*GST
    float* sW = gsm + 2 * 256 * GST;        // 2 x 128*GST

    const int tid = threadIdx.x;
    const int w = tid >> 5, lane = tid & 31;
    const int wm = w >> 1, wn = w & 1;
    const int g = lane >> 2, tig = lane & 3;
    const int row0 = blockIdx.y * 256;
    const int col0 = blockIdx.x * 128;

    const int lr = tid >> 3;            // 0..31
    const int lc = (tid & 7) << 2;      // 0,4,..28

    float acc[4][8][4];
#pragma unroll
    for (int mt = 0; mt < 4; mt++)
#pragma unroll
        for (int nt = 0; nt < 8; nt++)
#pragma unroll
            for (int i = 0; i < 4; i++) acc[mt][nt][i] = 0.f;

    const int T = K / 32;

    // preload tile 0
#pragma unroll
    for (int i = 0; i < 8; i++) {
        int r = lr + i * 32;
        float4 av = *(const float4*)&A[(size_t)(row0 + r) * K + lc];
        float* da = sA + r * GST + lc;
        da[0] = to_tf32(av.x); da[1] = to_tf32(av.y); da[2] = to_tf32(av.z); da[3] = to_tf32(av.w);
    }
#pragma unroll
    for (int i = 0; i < 4; i++) {
        int r = lr + i * 32;
        float4 wv = *(const float4*)&W[(size_t)(col0 + r) * K + lc];
        float* dw = sW + r * GST + lc;
        dw[0] = to_tf32(wv.x); dw[1] = to_tf32(wv.y); dw[2] = to_tf32(wv.z); dw[3] = to_tf32(wv.w);
    }
    __syncthreads();

    for (int t = 0; t < T; t++) {
        const int cur = t & 1;
        float4 av[8], wv[4];
        if (t + 1 < T) {
            const int k0 = (t + 1) * 32;
#pragma unroll
            for (int i = 0; i < 8; i++)
                av[i] = *(const float4*)&A[(size_t)(row0 + lr + i * 32) * K + k0 + lc];
#pragma unroll
            for (int i = 0; i < 4; i++)
                wv[i] = *(const float4*)&W[(size_t)(col0 + lr + i * 32) * K + k0 + lc];
        }

        const float* Ab = sA + cur * 256 * GST + (wm * 64 + g) * GST + tig;
        const float* Wb = sW + cur * 128 * GST + (wn * 64 + g) * GST + tig;
#pragma unroll
        for (int k8 = 0; k8 < 4; k8++) {
            const int ko = k8 * 8;
            float a[4][4];
#pragma unroll
            for (int mt = 0; mt < 4; mt++) {
                a[mt][0] = Ab[(mt * 16) * GST + ko];
                a[mt][1] = Ab[(mt * 16 + 8) * GST + ko];
                a[mt][2] = Ab[(mt * 16) * GST + ko + 4];
                a[mt][3] = Ab[(mt * 16 + 8) * GST + ko + 4];
            }
#pragma unroll
            for (int nt = 0; nt < 8; nt++) {
                float b0 = Wb[(nt * 8) * GST + ko];
                float b1 = Wb[(nt * 8) * GST + ko + 4];
#pragma unroll
                for (int mt = 0; mt < 4; mt++)
                    mma_tf32(acc[mt][nt], a[mt][0], a[mt][1], a[mt][2], a[mt][3], b0, b1);
            }
        }

        if (t + 1 < T) {
            const int nxt = 1 - cur;
            float* baseA = sA + nxt * 256 * GST;
            float* baseW = sW + nxt * 128 * GST;
            __syncthreads();
#pragma unroll
            for (int i = 0; i < 8; i++) {
                float* da = baseA + (lr + i * 32) * GST + lc;
                da[0] = to_tf32(av[i].x); da[1] = to_tf32(av[i].y);
                da[2] = to_tf32(av[i].z); da[3] = to_tf32(av[i].w);
            }
#pragma unroll
            for (int i = 0; i < 4; i++) {
                float* dw = baseW + (lr + i * 32) * GST + lc;
                dw[0] = to_tf32(wv[i].x); dw[1] = to_tf32(wv[i].y);
                dw[2] = to_tf32(wv[i].z); dw[3] = to_tf32(wv[i].w);
            }
            __syncthreads();
        }
    }

    // epilogue: bias + store
#pragma unroll
    for (int nt = 0; nt < 8; nt++) {
        const int col = col0 + wn * 64 + nt * 8 + 2 * tig;
        float2 bb = *(const float2*)&bias[col];
#pragma unroll
        for (int mt = 0; mt < 4; mt++) {
            const int rowA = row0 + wm * 64 + mt * 16 + g;
            *(float2*)&C[(size_t)rowA * N + col] =
                make_float2(acc[mt][nt][0] + bb.x, acc[mt][nt][1] + bb.y);
            *(float2*)&C[(size_t)(rowA + 8) * N + col] =
                make_float2(acc[mt][nt][2] + bb.x, acc[mt][nt][3] + bb.y);
        }
    }
}

// ---------------- lambda ----------------
__global__ void lam_kernel(const float* __restrict__ lq1, const float* __restrict__ lk1,
                           const float* __restrict__ lq2, const float* __restrict__ lk2) {
    int h = threadIdx.x;
    if (h < H_) {
        float d1 = 0.f, d2 = 0.f;
        for (int i = 0; i < 64; i++) {
            d1 += lq1[h * 64 + i] * lk1[h * 64 + i];
            d2 += lq2[h * 64 + i] * lk2[h * 64 + i];
        }
        g_lam[h] = LAMBDA_INIT + expf(d1) - expf(d2);
    }
}

// ---------------- TF32 dual-stream causal attention (R13/R14, 256 thr, passing) ----
__global__ __launch_bounds__(256, 1) void attn_kernel(const float* __restrict__ head_w) {
    extern __shared__ __align__(16) float smem[];
    float* sQ1 = smem;
    float* sQ2 = sQ1 + 64 * QST;
    float* sK1 = sQ2 + 64 * QST;
    float* sK2 = sK1 + 64 * QST;
    float* sP1 = sK2 + 64 * QST;
    float* sP2 = sP1 + 64 * QST;
    float* sV  = sP2 + 64 * QST;
    float* scratch = sK1;

    const int p = blockIdx.x, h = blockIdx.y, b = blockIdx.z;
    const int tid = threadIdx.x;
    const int w = tid >> 5, lane = tid & 31;
    const int st = w >> 2, wr = w & 3;
    const int g = lane >> 2, tig = lane & 3;
    const float lam = g_lam[h];

    float* sQ  = st ? sQ2 : sQ1;
    float* sKs = st ? sK2 : sK1;
    float* sP  = st ? sP2 : sP1;
    const int rAl = 16 * wr + g;

    for (int rep = 0; rep < 2; rep++) {
        const int qt = (rep == 0) ? p : (31 - p);

#pragma unroll
        for (int i = 0; i < 8; i++) {
            int idx = tid + i * 256;
            int strm = idx >> 10;
            int r = (idx >> 4) & 63;
            int c4 = idx & 15;
            float4 v = *(const float4*)&g_q[(size_t)(b * S_ + qt * 64 + r) * NQ_ + h * 128 + strm * 64 + c4 * 4];
            float* dst = (strm ? sQ2 : sQ1) + r * QST + c4 * 4;
            dst[0] = to_tf32(v.x * SCALE_QK);
            dst[1] = to_tf32(v.y * SCALE_QK);
            dst[2] = to_tf32(v.z * SCALE_QK);
            dst[3] = to_tf32(v.w * SCALE_QK);
        }

        float o[8][4];
#pragma unroll
        for (int n = 0; n < 8; n++) { o[n][0] = o[n][1] = o[n][2] = o[n][3] = 0.f; }
        float lA = 0.f, lB = 0.f;

        for (int kt = 0; kt <= qt; kt++) {
            __syncthreads();
#pragma unroll
            for (int i = 0; i < 12; i++) {
                int idx = tid + i * 256;
                if (idx < 2048) {
                    int strm = idx >> 10;
                    int r = (idx >> 4) & 63;
                    int c4 = idx & 15;
                    float4 v = *(const float4*)&g_k[(size_t)(b * S_ + kt * 64 + r) * NQ_ + h * 128 + strm * 64 + c4 * 4];
                    float* dst = (strm ? sK2 : sK1) + r * QST + c4 * 4;
                    dst[0] = to_tf32(v.x); dst[1] = to_tf32(v.y);
                    dst[2] = to_tf32(v.z); dst[3] = to_tf32(v.w);
                } else {
                    int j = idx - 2048;
                    int r = j >> 4;
                    int c4 = j & 15;
                    float4 v = *(const float4*)&g_v[(size_t)(b * S_ + kt * 64 + r) * D_ + h * 64 + c4 * 4];
                    float* dst = sV + r * VST + c4 * 4;
                    dst[0] = to_tf32(v.x); dst[1] = to_tf32(v.y);
                    dst[2] = to_tf32(v.z); dst[3] = to_tf32(v.w);
                }
            }
            __syncthreads();

            float s[8][4];
#pragma unroll
            for (int n = 0; n < 8; n++) { s[n][0] = s[n][1] = s[n][2] = s[n][3] = 0.f; }
            const float* Qb = sQ + rAl * QST + tig;
            const float* Kb = sKs + g * QST + tig;
#pragma unroll
            for (int k8 = 0; k8 < 8; k8++) {
                const int ko = 8 * k8;
                float a0 = Qb[ko];
                float a1 = Qb[8 * QST + ko];
                float a2 = Qb[ko + 4];
                float a3 = Qb[8 * QST + ko + 4];
#pragma unroll
                for (int np = 0; np < 8; np++) {
                    float b0 = Kb[np * 8 * QST + ko];
                    float b1 = Kb[np * 8 * QST + ko + 4];
                    mma_tf32(s[np], a0, a1, a2, a3, b0, b1);
                }
            }

            const bool diag = (kt == qt);
            float sumA = 0.f, sumB = 0.f;
#pragma unroll
            for (int n = 0; n < 8; n++) {
                int c0 = 8 * n + 2 * tig;
                float p00, p01, p10, p11;
                if (diag) {
                    p00 = (c0     > rAl)     ? 0.f : __expf(s[n][0]);
                    p01 = (c0 + 1 > rAl)     ? 0.f : __expf(s[n][1]);
                    p10 = (c0     > rAl + 8) ? 0.f : __expf(s[n][2]);
                    p11 = (c0 + 1 > rAl + 8) ? 0.f : __expf(s[n][3]);
                } else {
                    p00 = __expf(s[n][0]); p01 = __expf(s[n][1]);
                    p10 = __expf(s[n][2]); p11 = __expf(s[n][3]);
                }
                sumA += p00 + p01;
                sumB += p10 + p11;
                *(float2*)&sP[rAl * QST + c0]       = make_float2(to_tf32(p00), to_tf32(p01));
                *(float2*)&sP[(rAl + 8) * QST + c0] = make_float2(to_tf32(p10), to_tf32(p11));
            }
            sumA += __shfl_xor_sync(0xffffffffu, sumA, 1);
            sumA += __shfl_xor_sync(0xffffffffu, sumA, 2);
            sumB += __shfl_xor_sync(0xffffffffu, sumB, 1);
            sumB += __shfl_xor_sync(0xffffffffu, sumB, 2);
            lA += sumA;
            lB += sumB;
            __syncwarp();

            const float* Pb = sP + rAl * QST + tig;
#pragma unroll
            for (int k8 = 0; k8 < 8; k8++) {
                const int ko = 8 * k8;
                float a0 = Pb[ko];
                float a1 = Pb[8 * QST + ko];
                float a2 = Pb[ko + 4];
                float a3 = Pb[8 * QST + ko + 4];
#pragma unroll
                for (int np = 0; np < 8; np++) {
                    float b0 = sV[(ko + tig) * VST + 8 * np + g];
                    float b1 = sV[(ko + tig + 4) * VST + 8 * np + g];
                    mma_tf32(o[np], a0, a1, a2, a3, b0, b1);
                }
            }
            __syncwarp();
        }

        __syncthreads();
        if (st == 1) {
            float fA = lam / lA, fB = lam / lB;
#pragma unroll
            for (int n = 0; n < 8; n++) {
                int c0 = 8 * n + 2 * tig;
                *(float2*)&scratch[rAl * 66 + c0]       = make_float2(o[n][0] * fA, o[n][1] * fA);
                *(float2*)&scratch[(rAl + 8) * 66 + c0] = make_float2(o[n][2] * fB, o[n][3] * fB);
            }
        }
        __syncthreads();
        if (st == 0) {
            float fA = 1.f / lA, fB = 1.f / lB;
            float oA[16], oB[16];
            float ssA = 0.f, ssB = 0.f;
#pragma unroll
            for (int n = 0; n < 8; n++) {
                int c0 = 8 * n + 2 * tig;
                float2 sA2 = *(float2*)&scratch[rAl * 66 + c0];
                float2 sB2 = *(float2*)&scratch[(rAl + 8) * 66 + c0];
                oA[2 * n]     = o[n][0] * fA - sA2.x;
                oA[2 * n + 1] = o[n][1] * fA - sA2.y;
                oB[2 * n]     = o[n][2] * fB - sB2.x;
                oB[2 * n + 1] = o[n][3] * fB - sB2.y;
                ssA += oA[2 * n] * oA[2 * n] + oA[2 * n + 1] * oA[2 * n + 1];
                ssB += oB[2 * n] * oB[2 * n] + oB[2 * n + 1] * oB[2 * n + 1];
            }
            ssA += __shfl_xor_sync(0xffffffffu, ssA, 1);
            ssA += __shfl_xor_sync(0xffffffffu, ssA, 2);
            ssB += __shfl_xor_sync(0xffffffffu, ssB, 1);
            ssB += __shfl_xor_sync(0xffffffffu, ssB, 2);
            float rnA = rsqrtf(ssA * (1.f / 64.f) + 1e-6f);
            float rnB = rsqrtf(ssB * (1.f / 64.f) + 1e-6f);

            size_t rowA = (size_t)(b * S_ + qt * 64 + rAl) * D_ + h * 64;
            size_t rowB = rowA + (size_t)8 * D_;
#pragma unroll
            for (int n = 0; n < 8; n++) {
                int c0 = 8 * n + 2 * tig;
                float2 hw2 = *(const float2*)&head_w[h * 64 + c0];
                *(float2*)&g_y[rowA + c0] =
                    make_float2(oA[2 * n] * rnA * hw2.x * 0.8f, oA[2 * n + 1] * rnA * hw2.y * 0.8f);
                *(float2*)&g_y[rowB + c0] =
                    make_float2(oB[2 * n] * rnB * hw2.x * 0.8f, oB[2 * n + 1] * rnB * hw2.y * 0.8f);
            }
        }
        __syncthreads();
    }
}

// ---------------- launch ----------------
extern "C" void kernel_launch(void* const* d_in, const int* in_sizes, int n_in,
                              void* d_out, int out_size) {
    const float* x   = (const float*)d_in[0];
    const float* Wq  = (const float*)d_in[1];
    const float* bq  = (const float*)d_in[2];
    const float* Wk  = (const float*)d_in[3];
    const float* bk  = (const float*)d_in[4];
    const float* Wv  = (const float*)d_in[5];
    const float* bv  = (const float*)d_in[6];
    const float* Wo  = (const float*)d_in[7];
    const float* bo  = (const float*)d_in[8];
    const float* hw  = (const float*)d_in[9];
    const float* lq1 = (const float*)d_in[10];
    const float* lk1 = (const float*)d_in[11];
    const float* lq2 = (const float*)d_in[12];
    const float* lk2 = (const float*)d_in[13];
    float* out = (float*)d_out;

    float *pq, *pk, *pv, *py;
    cudaGetSymbolAddress((void**)&pq, g_q);
    cudaGetSymbolAddress((void**)&pk, g_k);
    cudaGetSymbolAddress((void**)&pv, g_v);
    cudaGetSymbolAddress((void**)&py, g_y);

    const int smem_attn = (6 * 64 * QST + 64 * VST) * (int)sizeof(float);   // 122880 B
    cudaFuncSetAttribute(attn_kernel, cudaFuncAttributeMaxDynamicSharedMemorySize, smem_attn);
    const int smem_gemm = 2 * (256 + 128) * GST * (int)sizeof(float);       // 110592 B
    cudaFuncSetAttribute(gemm_tf32, cudaFuncAttributeMaxDynamicSharedMemorySize, smem_gemm);

    dim3 blk(256);
    rope_table_kernel<<<S_, 32>>>();
    gemm_tf32<<<dim3(NQ_ / 128, MS_ / 256), blk, smem_gemm>>>(x, Wq, bq, pq, MS_, NQ_, D_);
    gemm_tf32<<<dim3(NQ_ / 128, MS_ / 256), blk, smem_gemm>>>(x, Wk, bk, pk, MS_, NQ_, D_);
    gemm_tf32<<<dim3(D_ / 128, MS_ / 256), blk, smem_gemm>>>(x, Wv, bv, pv, MS_, D_, D_);
    rope_kernel<<<MS_, 512>>>();
    lam_kernel<<<1, 32>>>(lq1, lk1, lq2, lk2);
    attn_kernel<<<dim3(16, H_, B_), blk, smem_attn>>>(hw);
    gemm_tf32<<<dim3(D_ / 128, MS_ / 256), blk, smem_gemm>>>(py, Wo, bo, out, MS_, D_, D_);
}